// round 4
// baseline (speedup 1.0000x reference)
#include <cuda_runtime.h>
#include <cstdint>

// Problem constants
#define T_STEPS 2048
#define BATCH   256
#define IN_DIM  64
#define HID     256

// Tiling: 16 clusters (row-groups) x 8 CTAs (j-split) = 128 CTAs
#define ROWS    16
#define CLUSTER 8

// smem layout (bytes):
//   h bufs : 4 x 16384  = [0, 65536)
//   x bufs : 4 x 4096   = [65536, 81920)
//   mbars  : full[4][4] at 81920 + (d*4+c)*8 ; empty[4] at 82048 + d*8
#define HBUF_B   16384
#define XOFF_B   65536
#define XBUF_B   4096
#define MBOFF    81920
#define FULL_OFF(d,c) (MBOFF + ((d)*4 + (c))*8)
#define EMPTY_OFF(d)  (MBOFF + 128 + (d)*8)
#define SMEM_BYTES    82304

// h trajectory for the output GEMM
__device__ float g_hs[(size_t)T_STEPS * BATCH * HID];

typedef unsigned long long ull;

// ---- packed fp32x2 helpers ----
__device__ __forceinline__ void fma2(ull& acc, ull a, ull b) {
    asm("fma.rn.f32x2 %0, %1, %2, %0;" : "+l"(acc) : "l"(a), "l"(b));
}
__device__ __forceinline__ float redpair(ull v) {
    float lo = __uint_as_float((unsigned int)(v & 0xffffffffULL));
    float hi = __uint_as_float((unsigned int)(v >> 32));
    return lo + hi;
}
__device__ __forceinline__ ull packf(float lo, float hi) {
    return (ull)__float_as_uint(lo) | ((ull)__float_as_uint(hi) << 32);
}
__device__ __forceinline__ float fast_tanh(float x) {
    float y;
    asm("tanh.approx.f32 %0, %1;" : "=f"(y) : "f"(x));
    return y;
}
__device__ __forceinline__ float sig_t(float x) {           // sigmoid via tanh (1 MUFU)
    return fmaf(fast_tanh(x * 0.5f), 0.5f, 0.5f);
}

// ---- cluster / mbarrier primitives ----
__device__ __forceinline__ uint32_t smem_u32(const void* p) {
    uint32_t a;
    asm("{ .reg .u64 t; cvta.to.shared.u64 t, %1; cvt.u32.u64 %0, t; }" : "=r"(a) : "l"(p));
    return a;
}
__device__ __forceinline__ uint32_t ctarank() {
    uint32_t r; asm("mov.u32 %0, %%cluster_ctarank;" : "=r"(r)); return r;
}
__device__ __forceinline__ uint32_t mapa_rank(uint32_t addr, uint32_t r) {
    uint32_t o; asm("mapa.shared::cluster.u32 %0, %1, %2;" : "=r"(o) : "r"(addr), "r"(r)); return o;
}
__device__ __forceinline__ void mbar_init(uint32_t addr, uint32_t count) {
    asm volatile("mbarrier.init.shared.b64 [%0], %1;" :: "r"(addr), "r"(count) : "memory");
}
__device__ __forceinline__ void mbar_arrive_rel(uint32_t addr) {
    asm volatile("mbarrier.arrive.release.cluster.shared::cluster.b64 _, [%0];" :: "r"(addr) : "memory");
}
__device__ __forceinline__ void mbar_wait(uint32_t addr, uint32_t parity) {
    uint32_t done;
    asm volatile(
        "{\n\t.reg .pred p;\n\t"
        "mbarrier.try_wait.parity.acquire.cluster.shared::cta.b64 p, [%1], %2;\n\t"
        "selp.b32 %0, 1, 0, p;\n\t}"
        : "=r"(done) : "r"(addr), "r"(parity) : "memory");
    while (!done) {
        asm volatile(
            "{\n\t.reg .pred p;\n\t"
            "mbarrier.try_wait.parity.acquire.cluster.shared::cta.b64 p, [%1], %2, 0x989680;\n\t"
            "selp.b32 %0, 1, 0, p;\n\t}"
            : "=r"(done) : "r"(addr), "r"(parity) : "memory");
    }
}
__device__ __forceinline__ void st_cluster(uint32_t addr, float v) {
    asm volatile("st.shared::cluster.f32 [%0], %1;" :: "r"(addr), "f"(v) : "memory");
}
__device__ __forceinline__ void cluster_sync_all() {
    asm volatile("barrier.cluster.arrive.aligned;" ::: "memory");
    asm volatile("barrier.cluster.wait.aligned;" ::: "memory");
}

// =====================================================================
// Persistent recurrent kernel: DSMEM-pipelined GRU
// =====================================================================
__global__ void __launch_bounds__(256, 1) __cluster_dims__(CLUSTER, 1, 1)
k_rec(
    const float* __restrict__ input,   // [T][B][I]
    const float* __restrict__ hidden,  // [1][B][3]
    const float* __restrict__ W_dec,   // [H][3]
    const float* __restrict__ b_dec,   // [H]
    const float* __restrict__ W_ih,    // [3H][I]
    const float* __restrict__ W_hh,    // [3H][H]
    const float* __restrict__ b_ih,    // [3H]
    const float* __restrict__ b_hh)    // [3H]
{
    extern __shared__ float sm[];
    const uint32_t sbase = smem_u32(sm);

    const int tid = threadIdx.x;
    const int lane = tid & 31;
    const int warp = tid >> 5;
    const int kslice = lane & 7;           // k in [kslice*32, kslice*32+32)
    const int jw = lane >> 3;              // j within warp (0..3)
    const int jloc = warp * 4 + jw;        // 0..31
    const uint32_t rank = ctarank();       // j-chunk
    const int grp = blockIdx.x >> 3;       // row group (cluster id)
    const int rbase = grp * ROWS;
    const int jg = (int)rank * 32 + jloc;  // global hidden column

    // swizzled float offset of column jg within an h row (16B-chunk XOR swizzle)
    const int jsw = (((jg >> 2) ^ ((jg >> 5) & 7)) << 2) + (jg & 3);

    // ---- mbarrier init ----
    if (tid == 0) {
        #pragma unroll
        for (int d = 0; d < 4; d++) {
            #pragma unroll
            for (int c = 0; c < 4; c++) mbar_init(sbase + FULL_OFF(d, c), 64);
            mbar_init(sbase + EMPTY_OFF(d), 64);
        }
    }

    // ---- weights into registers (packed f32x2) ----
    ull whr[16], whz[16], whn[16];
    ull wxr[4],  wxz[4],  wxn[4];
    {
        const float4* W4 = (const float4*)W_hh;   // row stride 64 float4
        #pragma unroll
        for (int c = 0; c < 8; c++) {
            float4 vr = __ldg(&W4[((size_t)(0 * HID + jg)) * 64 + kslice * 8 + c]);
            float4 vz = __ldg(&W4[((size_t)(1 * HID + jg)) * 64 + kslice * 8 + c]);
            float4 vn = __ldg(&W4[((size_t)(2 * HID + jg)) * 64 + kslice * 8 + c]);
            whr[2*c] = packf(vr.x, vr.y); whr[2*c+1] = packf(vr.z, vr.w);
            whz[2*c] = packf(vz.x, vz.y); whz[2*c+1] = packf(vz.z, vz.w);
            whn[2*c] = packf(vn.x, vn.y); whn[2*c+1] = packf(vn.z, vn.w);
        }
        const float4* X4 = (const float4*)W_ih;   // row stride 16 float4
        #pragma unroll
        for (int c = 0; c < 2; c++) {
            float4 vr = __ldg(&X4[((size_t)(0 * HID + jg)) * 16 + kslice * 2 + c]);
            float4 vz = __ldg(&X4[((size_t)(1 * HID + jg)) * 16 + kslice * 2 + c]);
            float4 vn = __ldg(&X4[((size_t)(2 * HID + jg)) * 16 + kslice * 2 + c]);
            wxr[2*c] = packf(vr.x, vr.y); wxr[2*c+1] = packf(vr.z, vr.w);
            wxz[2*c] = packf(vz.x, vz.y); wxz[2*c+1] = packf(vz.z, vz.w);
            wxn[2*c] = packf(vn.x, vn.y); wxn[2*c+1] = packf(vn.z, vn.w);
        }
    }

    const float bsum_r = b_ih[jg]           + b_hh[jg];
    const float bsum_z = b_ih[HID + jg]     + b_hh[HID + jg];
    const float bx_n   = b_ih[2 * HID + jg];
    const float bh_n   = b_hh[2 * HID + jg];

    // ---- prefill: h0 (full 16x256, swizzled) into buf 0, x0 = 0 ----
    for (int idx = tid; idx < ROWS * HID; idx += 256) {
        int row = idx >> 8;
        int col = idx & 255;
        int b = rbase + row;
        float v = b_dec[col]
                + hidden[b * 3 + 0] * W_dec[col * 3 + 0]
                + hidden[b * 3 + 1] * W_dec[col * 3 + 1]
                + hidden[b * 3 + 2] * W_dec[col * 3 + 2];
        int csw = (((col >> 2) ^ ((col >> 5) & 7)) << 2) + (col & 3);
        sm[row * HID + csw] = v;
    }
    for (int idx = tid; idx < ROWS * IN_DIM; idx += 256)
        sm[XOFF_B / 4 + idx] = 0.f;

    __syncthreads();
    cluster_sync_all();   // mbars + buf0 visible before any remote op

    // peer addresses
    const uint32_t peer_store = mapa_rank(sbase, (uint32_t)kslice);  // h stores -> rank kslice
    const uint32_t arr_peer   = mapa_rank(sbase, (uint32_t)(lane & 7)); // arrives (lanes 0..7)

    // x prefetch register: thread owns one float4 of the 16x64 tile
    const int xrow = tid >> 4, xchunk = tid & 15;
    const float4* xp = (const float4*)(input + ((size_t)(rbase + xrow)) * IN_DIM) + xchunk;
    float4 xr4 = __ldg(xp);                       // input[0] -> xs[1]
    const size_t xstride4 = (size_t)BATCH * IN_DIM / 4;

    const int TL = T_STEPS - 1;

    // ---------------- time-step loop (no __syncthreads inside) ----------------
    for (int s = 0; s < T_STEPS; s++) {
        const int cur = s & 3;
        const int dn  = (s + 1) & 3;
        const float* hcur = sm + cur * (HBUF_B / 4);
        const float* xcur = sm + XOFF_B / 4 + cur * (XBUF_B / 4);

        // backpressure: buffer dn free (consumers of step s-3 done)
        if (s >= 3 && s < TL) {
            uint32_t pe = (uint32_t)(((s - dn - 3) >> 2) & 1);
            mbar_wait(sbase + EMPTY_OFF(dn), pe);
        }
        // x for step s+1 (local), then prefetch next
        if (s < TL)
            *(float4*)(sm + XOFF_B / 4 + dn * (XBUF_B / 4) + xrow * IN_DIM + xchunk * 4) = xr4;
        if (s <= T_STEPS - 3)
            xr4 = __ldg(xp + (size_t)(s + 1) * xstride4);

        const uint32_t pf = (s > 0) ? (uint32_t)(((s - (cur ? cur : 4)) >> 2) & 1) : 0u;
        const uint32_t peer_hb = peer_store + (uint32_t)(dn * HBUF_B);

        #pragma unroll 1
        for (int c = 0; c < 4; c++) {
            if (s > 0) mbar_wait(sbase + FULL_OFF(cur, c), pf);

            #pragma unroll
            for (int q = 0; q < 2; q++) {
                const int rp = c * 2 + q;
                const float* hra = hcur + (2 * rp) * HID;
                const float* hrb = hra + HID;
                const float* xra = xcur + (2 * rp) * IN_DIM;
                const float* xrb = xra + IN_DIM;

                ull pra = 0, pza = 0, nha = 0, nxa = 0;
                ull prb = 0, pzb = 0, nhb = 0, nxb = 0;
                #pragma unroll
                for (int cc = 0; cc < 8; cc++) {
                    int p = (kslice << 3) + (cc ^ kslice);
                    ulonglong2 ha = *(const ulonglong2*)(hra + p * 4);
                    ulonglong2 hb = *(const ulonglong2*)(hrb + p * 4);
                    fma2(pra, ha.x, whr[2*cc]); fma2(pra, ha.y, whr[2*cc+1]);
                    fma2(pza, ha.x, whz[2*cc]); fma2(pza, ha.y, whz[2*cc+1]);
                    fma2(nha, ha.x, whn[2*cc]); fma2(nha, ha.y, whn[2*cc+1]);
                    fma2(prb, hb.x, whr[2*cc]); fma2(prb, hb.y, whr[2*cc+1]);
                    fma2(pzb, hb.x, whz[2*cc]); fma2(pzb, hb.y, whz[2*cc+1]);
                    fma2(nhb, hb.x, whn[2*cc]); fma2(nhb, hb.y, whn[2*cc+1]);
                }
                #pragma unroll
                for (int cc = 0; cc < 2; cc++) {
                    ulonglong2 xa = *(const ulonglong2*)(xra + (kslice * 2 + cc) * 4);
                    ulonglong2 xb = *(const ulonglong2*)(xrb + (kslice * 2 + cc) * 4);
                    fma2(pra, xa.x, wxr[2*cc]); fma2(pra, xa.y, wxr[2*cc+1]);
                    fma2(pza, xa.x, wxz[2*cc]); fma2(pza, xa.y, wxz[2*cc+1]);
                    fma2(nxa, xa.x, wxn[2*cc]); fma2(nxa, xa.y, wxn[2*cc+1]);
                    fma2(prb, xb.x, wxr[2*cc]); fma2(prb, xb.y, wxr[2*cc+1]);
                    fma2(pzb, xb.x, wxz[2*cc]); fma2(pzb, xb.y, wxz[2*cc+1]);
                    fma2(nxb, xb.x, wxn[2*cc]); fma2(nxb, xb.y, wxn[2*cc+1]);
                }
                float var = redpair(pra), vaz = redpair(pza), vah = redpair(nha), vax = redpair(nxa);
                float vbr = redpair(prb), vbz = redpair(pzb), vbh = redpair(nhb), vbx = redpair(nxb);
                #pragma unroll
                for (int m = 1; m <= 4; m <<= 1) {
                    var += __shfl_xor_sync(0xffffffffu, var, m);
                    vaz += __shfl_xor_sync(0xffffffffu, vaz, m);
                    vah += __shfl_xor_sync(0xffffffffu, vah, m);
                    vax += __shfl_xor_sync(0xffffffffu, vax, m);
                    vbr += __shfl_xor_sync(0xffffffffu, vbr, m);
                    vbz += __shfl_xor_sync(0xffffffffu, vbz, m);
                    vbh += __shfl_xor_sync(0xffffffffu, vbh, m);
                    vbx += __shfl_xor_sync(0xffffffffu, vbx, m);
                }

                // gates for rows 2rp, 2rp+1 (all lanes redundantly)
                float rga = sig_t(var + bsum_r);
                float zga = sig_t(vaz + bsum_z);
                float nga = fast_tanh(vax + bx_n + rga * (vah + bh_n));
                float holda = hra[jsw];
                float hna = zga * (holda - nga) + nga;

                float rgb = sig_t(vbr + bsum_r);
                float zgb = sig_t(vbz + bsum_z);
                float ngb = fast_tanh(vbx + bx_n + rgb * (vbh + bh_n));
                float holdb = hrb[jsw];
                float hnb = zgb * (holdb - ngb) + ngb;

                if (s < TL) {
                    uint32_t pa = peer_hb + (uint32_t)(((2 * rp) * HID + jsw) * 4);
                    st_cluster(pa, hna);
                    st_cluster(pa + HID * 4, hnb);
                }
                // trajectory store (one lane per row)
                size_t gi = ((size_t)s * BATCH + rbase + 2 * rp) * HID + jg;
                if (kslice == 0)      g_hs[gi] = hna;
                else if (kslice == 1) g_hs[gi + HID] = hnb;
            }

            if (s < TL) {
                __syncwarp();
                if (lane < 8) mbar_arrive_rel(arr_peer + FULL_OFF(dn, c));
            }
        }

        // all reads of buffer `cur` done -> signal empty to all cluster CTAs
        if (s < TL) {
            __syncwarp();
            if (lane < 8) mbar_arrive_rel(arr_peer + EMPTY_OFF(cur));
        }
    }

    cluster_sync_all();
}

// =====================================================================
// Output GEMM: out[b][t][o] = hs[t][b][:] . W_out[o][:] + b_out[o]
// =====================================================================
#define XPITCH 68
__global__ void __launch_bounds__(256) k_out(
    const float* __restrict__ W_out,   // [I][H]
    const float* __restrict__ b_out,   // [I]
    float* __restrict__ out)           // [B][T][I]
{
    __shared__ float hs_s[64 * XPITCH];
    __shared__ float ws_s[64 * XPITCH];
    const int tid = threadIdx.x;
    const int tx = tid & 15, ty = tid >> 4;
    const size_t mbase = (size_t)blockIdx.x * 64;

    ull acc[4][4];
    #pragma unroll
    for (int ii = 0; ii < 4; ii++)
        #pragma unroll
        for (int jj = 0; jj < 4; jj++) acc[ii][jj] = 0ULL;

    for (int kc = 0; kc < 4; kc++) {
        const int kofs = kc * 64;
        for (int i = tid; i < 1024; i += 256) {
            int row = i >> 4, c = i & 15;
            float4 v = *(const float4*)(g_hs + (mbase + row) * HID + kofs + c * 4);
            *(float4*)(hs_s + row * XPITCH + c * 4) = v;
        }
        for (int i = tid; i < 1024; i += 256) {
            int row = i >> 4, c = i & 15;
            float4 v = *(const float4*)(W_out + (size_t)row * HID + kofs + c * 4);
            *(float4*)(ws_s + row * XPITCH + c * 4) = v;
        }
        __syncthreads();
        #pragma unroll
        for (int k4 = 0; k4 < 16; k4++) {
            ulonglong2 a[4], w[4];
            #pragma unroll
            for (int ii = 0; ii < 4; ii++)
                a[ii] = *(const ulonglong2*)(hs_s + (ty * 4 + ii) * XPITCH + k4 * 4);
            #pragma unroll
            for (int jj = 0; jj < 4; jj++)
                w[jj] = *(const ulonglong2*)(ws_s + (jj * 16 + tx) * XPITCH + k4 * 4);
            #pragma unroll
            for (int ii = 0; ii < 4; ii++)
                #pragma unroll
                for (int jj = 0; jj < 4; jj++) {
                    fma2(acc[ii][jj], a[ii].x, w[jj].x);
                    fma2(acc[ii][jj], a[ii].y, w[jj].y);
                }
        }
        __syncthreads();
    }

    #pragma unroll
    for (int ii = 0; ii < 4; ii++) {
        size_t m = mbase + ty * 4 + ii;
        size_t t = m >> 8;
        size_t b = m & 255;
        float* op = out + (b * T_STEPS + t) * IN_DIM;
        #pragma unroll
        for (int jj = 0; jj < 4; jj++) {
            int o = jj * 16 + tx;
            op[o] = redpair(acc[ii][jj]) + b_out[o];
        }
    }
}

extern "C" void kernel_launch(void* const* d_in, const int* in_sizes, int n_in,
                              void* d_out, int out_size)
{
    const float* input  = (const float*)d_in[0];
    const float* hidden = (const float*)d_in[1];
    const float* W_dec  = (const float*)d_in[2];
    const float* b_dec  = (const float*)d_in[3];
    const float* W_ih   = (const float*)d_in[4];
    const float* W_hh   = (const float*)d_in[5];
    const float* b_ih   = (const float*)d_in[6];
    const float* b_hh   = (const float*)d_in[7];
    const float* W_out  = (const float*)d_in[8];
    const float* b_out  = (const float*)d_in[9];
    float* out = (float*)d_out;

    cudaFuncSetAttribute(k_rec, cudaFuncAttributeMaxDynamicSharedMemorySize, SMEM_BYTES);

    k_rec<<<128, 256, SMEM_BYTES>>>(input, hidden, W_dec, b_dec,
                                    W_ih, W_hh, b_ih, b_hh);
    k_out<<<(T_STEPS * BATCH) / 64, 256>>>(W_out, b_out, out);
}

// round 5
// speedup vs baseline: 2.3487x; 2.3487x over previous
#include <cuda_runtime.h>
#include <cstdint>

// Problem constants
#define T_STEPS 2048
#define BATCH   256
#define IN_DIM  64
#define HID     256

// Tiling: 16 row-groups x 8 j-CTAs = 128 CTAs.
#define GROUPS   16
#define JCTAS    8
#define ROWS     16
#define JW       32

// Device scratch
__device__ float g_hs[(size_t)T_STEPS * BATCH * HID];   // h trajectory [T][B][H]
__device__ float g_h[2][BATCH * HID];                   // double-buffered state
__device__ unsigned int g_arr[GROUPS * 32];             // per-group monotonic arrival counters

typedef unsigned long long ull;

// ---- packed fp32x2 helpers ----
__device__ __forceinline__ void fma2(ull& acc, ull a, ull b) {
    asm("fma.rn.f32x2 %0, %1, %2, %0;" : "+l"(acc) : "l"(a), "l"(b));
}
__device__ __forceinline__ float redpair(ull v) {
    float lo = __uint_as_float((unsigned int)(v & 0xffffffffULL));
    float hi = __uint_as_float((unsigned int)(v >> 32));
    return lo + hi;
}
__device__ __forceinline__ ull packf(float lo, float hi) {
    return (ull)__float_as_uint(lo) | ((ull)__float_as_uint(hi) << 32);
}
__device__ __forceinline__ float fast_sig(float x) {
    return __fdividef(1.f, 1.f + __expf(-x));
}
__device__ __forceinline__ float fast_tanh(float x) {
    float y;
    asm("tanh.approx.f32 %0, %1;" : "=f"(y) : "f"(x));
    return y;
}
__device__ __forceinline__ unsigned int ld_acq(const unsigned int* p) {
    unsigned int v;
    asm volatile("ld.acquire.gpu.global.u32 %0, [%1];" : "=r"(v) : "l"(p));
    return v;
}
__device__ __forceinline__ void red_release(unsigned int* p) {
    asm volatile("red.release.gpu.global.add.u32 [%0], %1;" :: "l"(p), "r"(1u) : "memory");
}
__device__ __forceinline__ uint32_t smem_u32(const void* p) {
    uint32_t a;
    asm("{ .reg .u64 t; cvta.to.shared.u64 t, %1; cvt.u32.u64 %0, t; }" : "=r"(a) : "l"(p));
    return a;
}
__device__ __forceinline__ void cp_async16(uint32_t saddr, const void* gaddr) {
    asm volatile("cp.async.cg.shared.global [%0], [%1], 16;" :: "r"(saddr), "l"(gaddr) : "memory");
}
__device__ __forceinline__ void cp_async_commit_wait() {
    asm volatile("cp.async.commit_group;" ::: "memory");
    asm volatile("cp.async.wait_group 0;" ::: "memory");
}

// =====================================================================
// Persistent recurrent kernel: register-resident weights,
// per-warp release/acquire sync through L2.
// =====================================================================
__global__ void __launch_bounds__(256, 1) k_rec(
    const float* __restrict__ input,   // [T][B][I]
    const float* __restrict__ hidden,  // [1][B][3]
    const float* __restrict__ W_dec,   // [H][3]
    const float* __restrict__ b_dec,   // [H]
    const float* __restrict__ W_ih,    // [3H][I]
    const float* __restrict__ W_hh,    // [3H][H]
    const float* __restrict__ b_ih,    // [3H]
    const float* __restrict__ b_hh)    // [3H]
{
    __shared__ float h_s[ROWS * HID];      // 16 KB, XOR-swizzled (16B-chunk granularity)
    __shared__ float x_s[ROWS * IN_DIM];   // 4 KB, linear

    const int tid = threadIdx.x;
    const int lane = tid & 31;
    const int warp = tid >> 5;
    const int kslice = lane & 7;          // k in [kslice*32, kslice*32+32)
    const int jw = lane >> 3;             // j within warp (0..3)
    const int jloc = warp * 4 + jw;       // 0..31
    const int grp = blockIdx.x >> 3;      // row group
    const int jc = blockIdx.x & 7;
    const int rbase = grp * ROWS;
    const int jbase = jc * JW;
    const int jg = jbase + jloc;          // global hidden column

    unsigned int* my_arr = &g_arr[grp * 32];
    const uint32_t hs_base = smem_u32(h_s);

    // swizzled float offset of column jg within an h_s row
    const int jsw = (((jg >> 2) ^ ((jg >> 5) & 7)) << 2) + (jg & 3);

    // --- load weights into registers (packed f32x2) ---
    ull whr[16], whz[16], whn[16];
    ull wxr[4],  wxz[4],  wxn[4];
    {
        const float4* W4 = (const float4*)W_hh;   // row stride 64 float4
        #pragma unroll
        for (int c = 0; c < 8; c++) {
            float4 vr = __ldg(&W4[((size_t)(0 * HID + jg)) * 64 + kslice * 8 + c]);
            float4 vz = __ldg(&W4[((size_t)(1 * HID + jg)) * 64 + kslice * 8 + c]);
            float4 vn = __ldg(&W4[((size_t)(2 * HID + jg)) * 64 + kslice * 8 + c]);
            whr[2*c] = packf(vr.x, vr.y); whr[2*c+1] = packf(vr.z, vr.w);
            whz[2*c] = packf(vz.x, vz.y); whz[2*c+1] = packf(vz.z, vz.w);
            whn[2*c] = packf(vn.x, vn.y); whn[2*c+1] = packf(vn.z, vn.w);
        }
        const float4* X4 = (const float4*)W_ih;   // row stride 16 float4
        #pragma unroll
        for (int c = 0; c < 2; c++) {
            float4 vr = __ldg(&X4[((size_t)(0 * HID + jg)) * 16 + kslice * 2 + c]);
            float4 vz = __ldg(&X4[((size_t)(1 * HID + jg)) * 16 + kslice * 2 + c]);
            float4 vn = __ldg(&X4[((size_t)(2 * HID + jg)) * 16 + kslice * 2 + c]);
            wxr[2*c] = packf(vr.x, vr.y); wxr[2*c+1] = packf(vr.z, vr.w);
            wxz[2*c] = packf(vz.x, vz.y); wxz[2*c+1] = packf(vz.z, vz.w);
            wxn[2*c] = packf(vn.x, vn.y); wxn[2*c+1] = packf(vn.z, vn.w);
        }
    }

    const float bsum_r = b_ih[jg]           + b_hh[jg];
    const float bsum_z = b_ih[HID + jg]     + b_hh[HID + jg];
    const float bx_n   = b_ih[2 * HID + jg];
    const float bh_n   = b_hh[2 * HID + jg];

    // --- h0: each CTA writes a 512-elem chunk of its own group's rows ---
    {
        int base = blockIdx.x * 512;
        for (int u = tid; u < 512; u += 256) {
            int idx = base + u;
            int b = idx >> 8;
            int j = idx & 255;
            g_h[0][idx] = b_dec[j]
                        + hidden[b * 3 + 0] * W_dec[j * 3 + 0]
                        + hidden[b * 3 + 1] * W_dec[j * 3 + 1]
                        + hidden[b * 3 + 2] * W_dec[j * 3 + 2];
        }
    }
    __syncthreads();
    if (lane == 0) red_release(my_arr);   // 8 arrivals per CTA, 64 per group

    const int r0 = kslice, r1 = kslice + 8;

    // x prefetch register: thread owns one float4 of the 16x64 tile
    const int xrow = tid >> 4, xchunk = tid & 15;
    const float4* xp = (const float4*)(input + ((size_t)(rbase + xrow)) * IN_DIM) + xchunk;
    float4 xr4 = __ldg(xp);                       // input[0] -> used at s=1
    const size_t xstride4 = (size_t)BATCH * IN_DIM / 4;

    // ---------------- time-step loop ----------------
    for (int s = 0; s < T_STEPS; s++) {
        // per-warp wait: h(s) ready when counter >= 64*(s+1)
        if (lane == 0) {
            unsigned int target = 64u * (unsigned int)(s + 1);
            while (ld_acq(my_arr) < target) { }
        }
        __syncwarp();

        // stage h tile [16][256] from g_h[s&1] via cp.async (L2 path, swizzled)
        {
            const float4* hsrc = (const float4*)(g_h[s & 1] + (size_t)rbase * HID);
            #pragma unroll
            for (int it = 0; it < 4; it++) {
                int idx = tid + it * 256;            // 0..1023
                int row = idx >> 6, c4 = idx & 63;
                int phys = c4 ^ ((c4 >> 3) & 7);
                cp_async16(hs_base + (uint32_t)((row * HID + phys * 4) * 4), hsrc + idx);
            }
        }
        // stage x tile [16][64] (xs[0]=0, xs[s]=input[s-1])
        if (s == 0) {
            *(float4*)(x_s + tid * 4) = make_float4(0.f, 0.f, 0.f, 0.f);
        } else {
            *(float4*)(x_s + tid * 4) = xr4;
        }
        if (s <= T_STEPS - 2)
            xr4 = __ldg(xp + (size_t)s * xstride4);

        cp_async_commit_wait();
        __syncthreads();

        float s0r, s0z, s0h, s0x, s1r, s1z, s1h, s1x;

        #pragma unroll 1
        for (int rp = 0; rp < 8; rp++) {
            const float* hra = h_s + (2 * rp)     * HID;
            const float* hrb = h_s + (2 * rp + 1) * HID;
            const float* xra = x_s + (2 * rp)     * IN_DIM;
            const float* xrb = x_s + (2 * rp + 1) * IN_DIM;
            ull pra = 0, pza = 0, nha = 0, nxa = 0;
            ull prb = 0, pzb = 0, nhb = 0, nxb = 0;
            #pragma unroll
            for (int c = 0; c < 8; c++) {
                int p = (kslice << 3) + (c ^ kslice);
                ulonglong2 ha = *(const ulonglong2*)(hra + p * 4);
                ulonglong2 hb = *(const ulonglong2*)(hrb + p * 4);
                fma2(pra, ha.x, whr[2*c]); fma2(pra, ha.y, whr[2*c+1]);
                fma2(pza, ha.x, whz[2*c]); fma2(pza, ha.y, whz[2*c+1]);
                fma2(nha, ha.x, whn[2*c]); fma2(nha, ha.y, whn[2*c+1]);
                fma2(prb, hb.x, whr[2*c]); fma2(prb, hb.y, whr[2*c+1]);
                fma2(pzb, hb.x, whz[2*c]); fma2(pzb, hb.y, whz[2*c+1]);
                fma2(nhb, hb.x, whn[2*c]); fma2(nhb, hb.y, whn[2*c+1]);
            }
            #pragma unroll
            for (int c = 0; c < 2; c++) {
                ulonglong2 xa = *(const ulonglong2*)(xra + (kslice * 2 + c) * 4);
                ulonglong2 xb = *(const ulonglong2*)(xrb + (kslice * 2 + c) * 4);
                fma2(pra, xa.x, wxr[2*c]); fma2(pra, xa.y, wxr[2*c+1]);
                fma2(pza, xa.x, wxz[2*c]); fma2(pza, xa.y, wxz[2*c+1]);
                fma2(nxa, xa.x, wxn[2*c]); fma2(nxa, xa.y, wxn[2*c+1]);
                fma2(prb, xb.x, wxr[2*c]); fma2(prb, xb.y, wxr[2*c+1]);
                fma2(pzb, xb.x, wxz[2*c]); fma2(pzb, xb.y, wxz[2*c+1]);
                fma2(nxb, xb.x, wxn[2*c]); fma2(nxb, xb.y, wxn[2*c+1]);
            }
            float var = redpair(pra), vaz = redpair(pza), vah = redpair(nha), vax = redpair(nxa);
            float vbr = redpair(prb), vbz = redpair(pzb), vbh = redpair(nhb), vbx = redpair(nxb);
            #pragma unroll
            for (int m = 1; m <= 4; m <<= 1) {
                var += __shfl_xor_sync(0xffffffffu, var, m);
                vaz += __shfl_xor_sync(0xffffffffu, vaz, m);
                vah += __shfl_xor_sync(0xffffffffu, vah, m);
                vax += __shfl_xor_sync(0xffffffffu, vax, m);
                vbr += __shfl_xor_sync(0xffffffffu, vbr, m);
                vbz += __shfl_xor_sync(0xffffffffu, vbz, m);
                vbh += __shfl_xor_sync(0xffffffffu, vbh, m);
                vbx += __shfl_xor_sync(0xffffffffu, vbx, m);
            }
            int ra = 2 * rp, rb = 2 * rp + 1;
            if (ra == r0) { s0r = var; s0z = vaz; s0h = vah; s0x = vax; }
            if (rb == r0) { s0r = vbr; s0z = vbz; s0h = vbh; s0x = vbx; }
            if (ra == r1) { s1r = var; s1z = vaz; s1h = vah; s1x = vax; }
            if (rb == r1) { s1r = vbr; s1z = vbz; s1h = vbh; s1x = vbx; }
        }

        // --- gate math + state update: this thread owns rows r0, r1 at column jg ---
        float* hnxt = g_h[(s & 1) ^ 1];
        {
            float hold = h_s[r0 * HID + jsw];
            float rg = fast_sig(s0r + bsum_r);
            float zg = fast_sig(s0z + bsum_z);
            float ng = fast_tanh(s0x + bx_n + rg * (s0h + bh_n));
            float hnew = zg * (hold - ng) + ng;
            hnxt[(rbase + r0) * HID + jg] = hnew;
            g_hs[((size_t)s * BATCH + rbase + r0) * HID + jg] = hnew;
        }
        {
            float hold = h_s[r1 * HID + jsw];
            float rg = fast_sig(s1r + bsum_r);
            float zg = fast_sig(s1z + bsum_z);
            float ng = fast_tanh(s1x + bx_n + rg * (s1h + bh_n));
            float hnew = zg * (hold - ng) + ng;
            hnxt[(rbase + r1) * HID + jg] = hnew;
            g_hs[((size_t)s * BATCH + rbase + r1) * HID + jg] = hnew;
        }

        // per-warp arrive: all lanes' stores -> syncwarp -> lane0 release
        __syncwarp();
        if (lane == 0) red_release(my_arr);
    }

    // reset counter for next graph replay (one CTA per group)
    if (jc == 0 && tid == 0) {
        unsigned int fin = 64u * (unsigned int)(T_STEPS + 1);
        while (ld_acq(my_arr) < fin) { }
        *my_arr = 0u;
        __threadfence();
    }
}

// =====================================================================
// Output GEMM: out[b][t][o] = hs[t][b][:] . W_out[o][:] + b_out[o]
// Tile: 128 rows x 64 o, thread tile 8x4, K chunks of 64
// =====================================================================
#define OPITCH 68
__global__ void __launch_bounds__(256) k_out(
    const float* __restrict__ W_out,   // [I][H]
    const float* __restrict__ b_out,   // [I]
    float* __restrict__ out)           // [B][T][I]
{
    __shared__ float hs_s[128 * OPITCH];   // 34816 B
    __shared__ float ws_s[64 * OPITCH];    // 17408 B
    const int tid = threadIdx.x;
    const int tx = tid & 15, ty = tid >> 4;
    const size_t mbase = (size_t)blockIdx.x * 128;

    ull acc[8][4];
    #pragma unroll
    for (int ii = 0; ii < 8; ii++)
        #pragma unroll
        for (int jj = 0; jj < 4; jj++) acc[ii][jj] = 0ULL;

    for (int kc = 0; kc < 4; kc++) {
        const int kofs = kc * 64;
        #pragma unroll
        for (int u = 0; u < 8; u++) {
            int i = tid + u * 256;           // 0..2047
            int row = i >> 4, c = i & 15;
            float4 v = *(const float4*)(g_hs + (mbase + row) * HID + kofs + c * 4);
            *(float4*)(hs_s + row * OPITCH + c * 4) = v;
        }
        #pragma unroll
        for (int u = 0; u < 4; u++) {
            int i = tid + u * 256;           // 0..1023
            int row = i >> 4, c = i & 15;
            float4 v = *(const float4*)(W_out + (size_t)row * HID + kofs + c * 4);
            *(float4*)(ws_s + row * OPITCH + c * 4) = v;
        }
        __syncthreads();
        #pragma unroll
        for (int k4 = 0; k4 < 16; k4++) {
            ulonglong2 w[4];
            #pragma unroll
            for (int jj = 0; jj < 4; jj++)
                w[jj] = *(const ulonglong2*)(ws_s + (tx * 4 + jj) * OPITCH + k4 * 4);
            #pragma unroll
            for (int ii = 0; ii < 8; ii++) {
                ulonglong2 a = *(const ulonglong2*)(hs_s + (ty * 8 + ii) * OPITCH + k4 * 4);
                #pragma unroll
                for (int jj = 0; jj < 4; jj++) {
                    fma2(acc[ii][jj], a.x, w[jj].x);
                    fma2(acc[ii][jj], a.y, w[jj].y);
                }
            }
        }
        __syncthreads();
    }

    float4 bo = *(const float4*)(b_out + tx * 4);
    #pragma unroll
    for (int ii = 0; ii < 8; ii++) {
        size_t m = mbase + ty * 8 + ii;
        size_t t = m >> 8;
        size_t b = m & 255;
        float4 r;
        r.x = redpair(acc[ii][0]) + bo.x;
        r.y = redpair(acc[ii][1]) + bo.y;
        r.z = redpair(acc[ii][2]) + bo.z;
        r.w = redpair(acc[ii][3]) + bo.w;
        *(float4*)(out + (b * T_STEPS + t) * IN_DIM + tx * 4) = r;
    }
}

extern "C" void kernel_launch(void* const* d_in, const int* in_sizes, int n_in,
                              void* d_out, int out_size)
{
    const float* input  = (const float*)d_in[0];
    const float* hidden = (const float*)d_in[1];
    const float* W_dec  = (const float*)d_in[2];
    const float* b_dec  = (const float*)d_in[3];
    const float* W_ih   = (const float*)d_in[4];
    const float* W_hh   = (const float*)d_in[5];
    const float* b_ih   = (const float*)d_in[6];
    const float* b_hh   = (const float*)d_in[7];
    const float* W_out  = (const float*)d_in[8];
    const float* b_out  = (const float*)d_in[9];
    float* out = (float*)d_out;

    k_rec<<<GROUPS * JCTAS, 256>>>(input, hidden, W_dec, b_dec,
                                   W_ih, W_hh, b_ih, b_hh);
    k_out<<<(T_STEPS * BATCH) / 128, 256>>>(W_out, b_out, out);
}